// round 3
// baseline (speedup 1.0000x reference)
#include <cuda_runtime.h>
#include <math.h>

#define BB 64
#define SS 64
#define HH 1024
#define TT 40
#define VV 32000

// ---------------- scratch (device globals; no allocation allowed) ----------
__device__ float g_keysU[BB * SS * HH];   // 16.8 MB
__device__ float g_h[BB * HH];
__device__ float g_q[BB * HH];
__device__ float g_ctx[BB * HH];
__device__ float g_x[BB * 2 * HH];
__device__ float g_gi[BB * 3 * HH];
__device__ float g_gh[BB * 3 * HH];
__device__ float g_logits[BB * VV];       // 8.2 MB

// ---------------------------------------------------------------------------
// Generic fp32 GEMM: C[M,N] = A[M,K] @ B[N,K]^T (+ bias[n])
// Tile 64x64, BK=16, 256 threads, 4x4 microtile.
// grid = (N/64, M/64, splitK). atomic=1 -> atomicAdd partial sums (C must be
// pre-initialized with bias); atomic=0 -> direct store with bias.
// ---------------------------------------------------------------------------
__global__ void gemm_tn(const float* __restrict__ A, const float* __restrict__ Bm,
                        const float* __restrict__ bias, float* __restrict__ C,
                        int N, int K, int kChunk, int atomic)
{
    __shared__ float As[16][64];
    __shared__ float Bs[16][64];
    const int m0 = blockIdx.y * 64;
    const int n0 = blockIdx.x * 64;
    const int k0 = blockIdx.z * kChunk;
    const int tid = threadIdx.x;
    const int tx = tid & 15;          // n-direction (16)
    const int ty = tid >> 4;          // m-direction (16)
    const int lrow = tid >> 2;        // 0..63 load row
    const int lcol = (tid & 3) << 2;  // 0,4,8,12 load k-offset

    float acc[4][4];
#pragma unroll
    for (int i = 0; i < 4; i++)
#pragma unroll
        for (int j = 0; j < 4; j++) acc[i][j] = 0.f;

    const float* Ap = A + (long)(m0 + lrow) * K + k0 + lcol;
    const float* Bp = Bm + (long)(n0 + lrow) * K + k0 + lcol;

    for (int kt = 0; kt < kChunk; kt += 16) {
        float4 av = *(const float4*)(Ap + kt);
        float4 bv = *(const float4*)(Bp + kt);
        __syncthreads();
        As[lcol + 0][lrow] = av.x; As[lcol + 1][lrow] = av.y;
        As[lcol + 2][lrow] = av.z; As[lcol + 3][lrow] = av.w;
        Bs[lcol + 0][lrow] = bv.x; Bs[lcol + 1][lrow] = bv.y;
        Bs[lcol + 2][lrow] = bv.z; Bs[lcol + 3][lrow] = bv.w;
        __syncthreads();
#pragma unroll
        for (int kk = 0; kk < 16; kk++) {
            float4 a = *(const float4*)&As[kk][ty << 2];
            float4 b = *(const float4*)&Bs[kk][tx << 2];
            acc[0][0] += a.x * b.x; acc[0][1] += a.x * b.y;
            acc[0][2] += a.x * b.z; acc[0][3] += a.x * b.w;
            acc[1][0] += a.y * b.x; acc[1][1] += a.y * b.y;
            acc[1][2] += a.y * b.z; acc[1][3] += a.y * b.w;
            acc[2][0] += a.z * b.x; acc[2][1] += a.z * b.y;
            acc[2][2] += a.z * b.z; acc[2][3] += a.z * b.w;
            acc[3][0] += a.w * b.x; acc[3][1] += a.w * b.y;
            acc[3][2] += a.w * b.z; acc[3][3] += a.w * b.w;
        }
    }

#pragma unroll
    for (int i = 0; i < 4; i++) {
        const int row = m0 + (ty << 2) + i;
        const int col = n0 + (tx << 2);
        float* cp = C + (long)row * N + col;
        if (atomic) {
            atomicAdd(cp + 0, acc[i][0]);
            atomicAdd(cp + 1, acc[i][1]);
            atomicAdd(cp + 2, acc[i][2]);
            atomicAdd(cp + 3, acc[i][3]);
        } else {
            float4 o;
            o.x = acc[i][0] + bias[col + 0];
            o.y = acc[i][1] + bias[col + 1];
            o.z = acc[i][2] + bias[col + 2];
            o.w = acc[i][3] + bias[col + 3];
            *(float4*)cp = o;
        }
    }
}

// ---------------------------------------------------------------------------
// Per-step bias init for the three atomic GEMM outputs (q, gi, gh)
// ---------------------------------------------------------------------------
__global__ void init_step(const float* __restrict__ ba,
                          const float* __restrict__ b_ih,
                          const float* __restrict__ b_hh)
{
    int idx = blockIdx.x * 256 + threadIdx.x;
    const int nq = BB * HH;
    const int ng = BB * 3 * HH;
    if (idx < nq) {
        g_q[idx] = ba[idx % HH];
    } else if (idx < nq + ng) {
        int i = idx - nq;
        g_gi[i] = b_ih[i % (3 * HH)];
    } else if (idx < nq + 2 * ng) {
        int i = idx - nq - ng;
        g_gh[i] = b_hh[i % (3 * HH)];
    }
}

__global__ void copy_h0(const float* __restrict__ h0)
{
    int i = blockIdx.x * 256 + threadIdx.x;
    if (i < BB * HH) g_h[i] = h0[i];
}

__global__ void write_hidden(float* __restrict__ out_hid)
{
    int i = blockIdx.x * 256 + threadIdx.x;
    if (i < BB * HH) out_hid[i] = g_h[i];
}

// ---------------------------------------------------------------------------
// Attention: one block per batch element b.
// scores[s] = Va . tanh(q[b] + keysU[b,s]) + bv ; softmax over S ;
// ctx[b] = sum_s w[s] * EO[b,s,:]. Also writes attentions output.
// ---------------------------------------------------------------------------
__global__ void attn_step(const float* __restrict__ EO,
                          const float* __restrict__ Va,
                          const float* __restrict__ bv,
                          float* __restrict__ out_attn, int t)
{
    __shared__ float qs[HH];
    __shared__ float sc[SS];
    __shared__ float w[SS];
    const int b = blockIdx.x;
    const int tid = threadIdx.x;
    const int warp = tid >> 5, lane = tid & 31;

    for (int i = tid; i < HH; i += 256) qs[i] = g_q[b * HH + i];
    __syncthreads();

    for (int s = warp; s < SS; s += 8) {
        const float* kp = &g_keysU[((long)(b * SS + s)) * HH];
        float sum = 0.f;
        for (int h = lane; h < HH; h += 32)
            sum += tanhf(qs[h] + kp[h]) * Va[h];
#pragma unroll
        for (int o = 16; o; o >>= 1) sum += __shfl_xor_sync(~0u, sum, o);
        if (!lane) sc[s] = sum + bv[0];
    }
    __syncthreads();

    if (warp == 0) {
        float v0 = sc[lane], v1 = sc[lane + 32];
        float mx = fmaxf(v0, v1);
#pragma unroll
        for (int o = 16; o; o >>= 1) mx = fmaxf(mx, __shfl_xor_sync(~0u, mx, o));
        float e0 = expf(v0 - mx), e1 = expf(v1 - mx);
        float sm = e0 + e1;
#pragma unroll
        for (int o = 16; o; o >>= 1) sm += __shfl_xor_sync(~0u, sm, o);
        float inv = 1.f / sm;
        w[lane] = e0 * inv;
        w[lane + 32] = e1 * inv;
        out_attn[((long)(b * TT + t)) * SS + lane] = e0 * inv;
        out_attn[((long)(b * TT + t)) * SS + lane + 32] = e1 * inv;
    }
    __syncthreads();

    for (int h = tid; h < HH; h += 256) {
        float acc = 0.f;
        const float* ep = &EO[(long)b * SS * HH + h];
#pragma unroll 8
        for (int s = 0; s < SS; s++) acc += w[s] * ep[s * HH];
        g_ctx[b * HH + h] = acc;
    }
}

// x[b] = concat(embedding[token_t[b]], ctx[b])
__global__ void build_x(const int* __restrict__ target,
                        const float* __restrict__ emb, int t)
{
    const int b = blockIdx.x;
    const int tok = (t == 0) ? 0 : target[b * TT + t - 1];  // SOS_INDEX = 0
    const float* e = emb + (long)tok * HH;
    for (int i = threadIdx.x; i < 2 * HH; i += 256)
        g_x[b * 2 * HH + i] = (i < HH) ? e[i] : g_ctx[b * HH + (i - HH)];
}

// GRU pointwise; updates g_h in place
__global__ void gru_step()
{
    const int b = blockIdx.x;
    for (int j = threadIdx.x; j < HH; j += 256) {
        const int gbase = b * 3 * HH;
        float ir = g_gi[gbase + j];
        float iz = g_gi[gbase + HH + j];
        float in = g_gi[gbase + 2 * HH + j];
        float hr = g_gh[gbase + j];
        float hz = g_gh[gbase + HH + j];
        float hn = g_gh[gbase + 2 * HH + j];
        float r = 1.f / (1.f + expf(-(ir + hr)));
        float z = 1.f / (1.f + expf(-(iz + hz)));
        float n = tanhf(in + r * hn);
        float ho = g_h[b * HH + j];
        g_h[b * HH + j] = (1.f - z) * n + z * ho;
    }
}

// log_softmax over V per batch row; writes decoder_outputs[b, t, :]
__global__ void logsoftmax_step(float* __restrict__ out_dec, int t)
{
    __shared__ float red[256];
    const int b = blockIdx.x;
    const int tid = threadIdx.x;
    const float* lg = &g_logits[(long)b * VV];

    float mx = -1e30f;
    for (int v = tid; v < VV; v += 256) mx = fmaxf(mx, lg[v]);
    red[tid] = mx; __syncthreads();
    for (int s = 128; s; s >>= 1) {
        if (tid < s) red[tid] = fmaxf(red[tid], red[tid + s]);
        __syncthreads();
    }
    mx = red[0];
    __syncthreads();

    float sum = 0.f;
    for (int v = tid; v < VV; v += 256) sum += expf(lg[v] - mx);
    red[tid] = sum; __syncthreads();
    for (int s = 128; s; s >>= 1) {
        if (tid < s) red[tid] += red[tid + s];
        __syncthreads();
    }
    const float lse = mx + logf(red[0]);

    float* op = &out_dec[((long)(b * TT + t)) * VV];
    for (int v = tid; v < VV; v += 256) op[v] = lg[v] - lse;
}

// ---------------------------------------------------------------------------
extern "C" void kernel_launch(void* const* d_in, const int* in_sizes, int n_in,
                              void* d_out, int out_size)
{
    const float* EO     = (const float*)d_in[0];   // [B,S,H]
    const float* h0     = (const float*)d_in[1];   // [B,H]
    const int*   target = (const int*)  d_in[2];   // [B,T]
    const float* emb    = (const float*)d_in[3];   // [V,H]
    const float* Wa     = (const float*)d_in[4];   // [H,H]
    const float* ba     = (const float*)d_in[5];
    const float* Ua     = (const float*)d_in[6];   // [H,H]
    const float* bu     = (const float*)d_in[7];
    const float* Va     = (const float*)d_in[8];   // [1,H]
    const float* bvp    = (const float*)d_in[9];
    const float* W_ih   = (const float*)d_in[10];  // [3H,2H]
    const float* W_hh   = (const float*)d_in[11];  // [3H,H]
    const float* b_ih   = (const float*)d_in[12];
    const float* b_hh   = (const float*)d_in[13];
    const float* W_out  = (const float*)d_in[14];  // [V,H]
    const float* b_out  = (const float*)d_in[15];

    float* out      = (float*)d_out;
    float* out_dec  = out;                                 // [B,T,V]
    float* out_hid  = out + (long)BB * TT * VV;            // [1,B,H]
    float* out_attn = out_hid + (long)BB * HH;             // [B,T,S]

    float *p_keysU, *p_h, *p_q, *p_x, *p_gi, *p_gh, *p_logits;
    cudaGetSymbolAddress((void**)&p_keysU,  g_keysU);
    cudaGetSymbolAddress((void**)&p_h,      g_h);
    cudaGetSymbolAddress((void**)&p_q,      g_q);
    cudaGetSymbolAddress((void**)&p_x,      g_x);
    cudaGetSymbolAddress((void**)&p_gi,     g_gi);
    cudaGetSymbolAddress((void**)&p_gh,     g_gh);
    cudaGetSymbolAddress((void**)&p_logits, g_logits);

    // h = encoder_hidden
    copy_h0<<<(BB * HH + 255) / 256, 256>>>(h0);

    // keysU = EO @ Ua^T + bu   (M = B*S = 4096, N = H, K = H)
    gemm_tn<<<dim3(HH / 64, (BB * SS) / 64, 1), 256>>>(EO, Ua, bu, p_keysU,
                                                       HH, HH, HH, 0);

    const int initBlocks = (BB * HH + 2 * BB * 3 * HH + 255) / 256;

    for (int t = 0; t < TT; t++) {
        // bias-init q / gi / gh for atomic split-K accumulation
        init_step<<<initBlocks, 256>>>(ba, b_ih, b_hh);

        // q = h @ Wa^T + ba      (M=64, N=1024, K=1024, splitK=4)
        gemm_tn<<<dim3(HH / 64, 1, 4), 256>>>(p_h, Wa, nullptr, p_q,
                                              HH, HH, HH / 4, 1);

        attn_step<<<BB, 256>>>(EO, Va, bvp, out_attn, t);
        build_x<<<BB, 256>>>(target, emb, t);

        // gi = x @ W_ih^T + b_ih (M=64, N=3072, K=2048, splitK=4)
        gemm_tn<<<dim3(3 * HH / 64, 1, 4), 256>>>(p_x, W_ih, nullptr, p_gi,
                                                  3 * HH, 2 * HH, 2 * HH / 4, 1);
        // gh = h @ W_hh^T + b_hh (M=64, N=3072, K=1024, splitK=4)
        gemm_tn<<<dim3(3 * HH / 64, 1, 4), 256>>>(p_h, W_hh, nullptr, p_gh,
                                                  3 * HH, HH, HH / 4, 1);

        gru_step<<<BB, 256>>>();

        // logits = h_new @ W_out^T + b_out  (M=64, N=32000, K=1024)
        gemm_tn<<<dim3(VV / 64, 1, 1), 256>>>(p_h, W_out, b_out, p_logits,
                                              VV, HH, HH, 0);

        logsoftmax_step<<<BB, 256>>>(out_dec, t);
    }

    write_hidden<<<(BB * HH + 255) / 256, 256>>>(out_hid);
}

// round 4
// speedup vs baseline: 2.9848x; 2.9848x over previous
#include <cuda_runtime.h>
#include <cuda_bf16.h>
#include <math.h>

#define BB 64
#define SS 64
#define HH 1024
#define TT 40
#define VV 32000

// ---------------- scratch (device globals; no allocation allowed) ----------
__device__ float g_keysU[BB * SS * HH];                 // 16.8 MB fp32
__device__ float g_h[BB * HH];
__device__ float g_q[BB * HH];
__device__ float g_x[BB * 2 * HH];
__device__ float g_gi[BB * 3 * HH];
__device__ float g_gh[BB * 3 * HH];
__device__ float g_logits[BB * VV];                     // 8.2 MB
__device__ float g_scores[BB * SS];
__device__ __nv_bfloat16 g_wout16[(long)VV * HH];       // 65.5 MB
__device__ __nv_bfloat16 g_eo16[BB * SS * HH];          // 8.4 MB
__device__ __nv_bfloat16 g_ua16[HH * HH];               // 2 MB
__device__ __nv_bfloat16 g_h16[BB * HH];

// ---------------------------------------------------------------------------
// helpers
// ---------------------------------------------------------------------------
__device__ __forceinline__ float fast_tanh(float x) {
    float y;
    asm("tanh.approx.f32 %0, %1;" : "=f"(y) : "f"(x));
    return y;
}
__device__ __forceinline__ unsigned sptr(const void* p) {
    return (unsigned)__cvta_generic_to_shared(p);
}
__device__ __forceinline__ void cpa16(unsigned dst, const void* src) {
    asm volatile("cp.async.cg.shared.global [%0], [%1], 16;" :: "r"(dst), "l"(src));
}
__device__ __forceinline__ void ldm4(unsigned* r, unsigned addr) {
    asm volatile("ldmatrix.sync.aligned.m8n8.x4.shared.b16 {%0,%1,%2,%3}, [%4];"
                 : "=r"(r[0]), "=r"(r[1]), "=r"(r[2]), "=r"(r[3]) : "r"(addr));
}
__device__ __forceinline__ void mma_bf16(float* d, const unsigned* a,
                                         unsigned b0, unsigned b1) {
    asm volatile(
        "mma.sync.aligned.m16n8k16.row.col.f32.bf16.bf16.f32 "
        "{%0,%1,%2,%3}, {%4,%5,%6,%7}, {%8,%9}, {%0,%1,%2,%3};"
        : "+f"(d[0]), "+f"(d[1]), "+f"(d[2]), "+f"(d[3])
        : "r"(a[0]), "r"(a[1]), "r"(a[2]), "r"(a[3]), "r"(b0), "r"(b1));
}

// ---------------------------------------------------------------------------
// fp32 -> bf16 conversion (4 elems/thread)
// ---------------------------------------------------------------------------
__global__ void conv_bf16(const float* __restrict__ s, __nv_bfloat16* __restrict__ d)
{
    long i = ((long)blockIdx.x * 256 + threadIdx.x) * 4;
    float4 v = *(const float4*)(s + i);
    __nv_bfloat162* dp = (__nv_bfloat162*)(d + i);
    dp[0] = __floats2bfloat162_rn(v.x, v.y);
    dp[1] = __floats2bfloat162_rn(v.z, v.w);
}

// ---------------------------------------------------------------------------
// bf16 tensor-core GEMM: C[M,N] = A[M,K] @ B[N,K]^T + bias
// Block tile 64(M) x 128(N), K-chunk 64, 8 warps (2x4), m16n8k16 HMMA,
// cp.async double-buffered smem with xor swizzle (128B rows, 16B chunks).
// grid = (N/128, M/64). K multiple of 64.
// ---------------------------------------------------------------------------
__global__ void gemm_bf16_mma(const __nv_bfloat16* __restrict__ A,
                              const __nv_bfloat16* __restrict__ Bw,
                              const float* __restrict__ bias,
                              float* __restrict__ C, int K, int N)
{
    __shared__ __align__(1024) unsigned char smem_raw[49152]; // 2 * (8K A + 16K B)
    const unsigned sb0 = sptr(smem_raw);
    const int tid = threadIdx.x;
    const int wid = tid >> 5, lane = tid & 31;
    const int warp_m = wid >> 2;   // 0..1
    const int warp_n = wid & 3;    // 0..3
    const int n0 = blockIdx.x * 128;
    const int m0 = blockIdx.y * 64;
    const int kChunks = K >> 6;

    float acc[2][4][4];
#pragma unroll
    for (int a = 0; a < 2; a++)
#pragma unroll
        for (int b = 0; b < 4; b++)
#pragma unroll
            for (int c = 0; c < 4; c++) acc[a][b][c] = 0.f;

    // stage copy: 512 A-chunks (64 rows x 8) + 1024 B-chunks (128 rows x 8)
    auto stage = [&](unsigned sbase, int kc) {
#pragma unroll
        for (int i = 0; i < 6; i++) {
            int idx = tid + i * 256;
            if (idx < 512) {
                int r = idx >> 3, c = idx & 7;
                unsigned dst = sbase + (unsigned)(((r << 3) + (c ^ (r & 7))) << 4);
                cpa16(dst, A + (long)(m0 + r) * K + kc * 64 + c * 8);
            } else {
                int j = idx - 512;
                int r = j >> 3, c = j & 7;
                unsigned dst = sbase + 8192u + (unsigned)(((r << 3) + (c ^ (r & 7))) << 4);
                cpa16(dst, Bw + (long)(n0 + r) * K + kc * 64 + c * 8);
            }
        }
    };

    stage(sb0, 0);
    asm volatile("cp.async.commit_group;");

    for (int kc = 0; kc < kChunks; kc++) {
        if (kc + 1 < kChunks) stage(sb0 + ((kc + 1) & 1) * 24576u, kc + 1);
        asm volatile("cp.async.commit_group;");
        asm volatile("cp.async.wait_group 1;");
        __syncthreads();

        const unsigned bA = sb0 + (kc & 1) * 24576u;
        const unsigned bB = bA + 8192u;

#pragma unroll
        for (int kk = 0; kk < 4; kk++) {
            unsigned afr[2][4], bfr[2][4];
#pragma unroll
            for (int mt = 0; mt < 2; mt++) {
                int r = warp_m * 32 + mt * 16 + (lane & 15);
                int c = 2 * kk + (lane >> 4);
                ldm4(afr[mt], bA + (unsigned)(((r << 3) + (c ^ (r & 7))) << 4));
            }
#pragma unroll
            for (int np = 0; np < 2; np++) {
                int r = warp_n * 32 + np * 16 + ((lane >> 4) << 3) + (lane & 7);
                int c = 2 * kk + ((lane >> 3) & 1);
                ldm4(bfr[np], bB + (unsigned)(((r << 3) + (c ^ (r & 7))) << 4));
            }
#pragma unroll
            for (int mt = 0; mt < 2; mt++)
#pragma unroll
                for (int nt = 0; nt < 4; nt++)
                    mma_bf16(acc[mt][nt], afr[mt],
                             bfr[nt >> 1][(nt & 1) * 2], bfr[nt >> 1][(nt & 1) * 2 + 1]);
        }
        __syncthreads();
    }

#pragma unroll
    for (int mt = 0; mt < 2; mt++) {
        int row = m0 + warp_m * 32 + mt * 16 + (lane >> 2);
#pragma unroll
        for (int nt = 0; nt < 4; nt++) {
            int col = n0 + warp_n * 32 + nt * 8 + ((lane & 3) << 1);
            float* cp = C + (long)row * N + col;
            float b0 = bias[col], b1 = bias[col + 1];
            float2 v0 = {acc[mt][nt][0] + b0, acc[mt][nt][1] + b1};
            float2 v1 = {acc[mt][nt][2] + b0, acc[mt][nt][3] + b1};
            *(float2*)cp = v0;
            *(float2*)(cp + (long)8 * N) = v1;
        }
    }
}

// ---------------------------------------------------------------------------
// fp32 GEMM (small per-step GEMMs): C[M,N] = A[M,K] @ B[N,K]^T, split-K atomic
// ---------------------------------------------------------------------------
__global__ void gemm_tn(const float* __restrict__ A, const float* __restrict__ Bm,
                        float* __restrict__ C, int N, int K, int kChunk)
{
    __shared__ float As[16][64];
    __shared__ float Bs[16][64];
    const int m0 = blockIdx.y * 64;
    const int n0 = blockIdx.x * 64;
    const int k0 = blockIdx.z * kChunk;
    const int tid = threadIdx.x;
    const int tx = tid & 15;
    const int ty = tid >> 4;
    const int lrow = tid >> 2;
    const int lcol = (tid & 3) << 2;

    float acc[4][4];
#pragma unroll
    for (int i = 0; i < 4; i++)
#pragma unroll
        for (int j = 0; j < 4; j++) acc[i][j] = 0.f;

    const float* Ap = A + (long)(m0 + lrow) * K + k0 + lcol;
    const float* Bp = Bm + (long)(n0 + lrow) * K + k0 + lcol;

    for (int kt = 0; kt < kChunk; kt += 16) {
        float4 av = *(const float4*)(Ap + kt);
        float4 bv = *(const float4*)(Bp + kt);
        __syncthreads();
        As[lcol + 0][lrow] = av.x; As[lcol + 1][lrow] = av.y;
        As[lcol + 2][lrow] = av.z; As[lcol + 3][lrow] = av.w;
        Bs[lcol + 0][lrow] = bv.x; Bs[lcol + 1][lrow] = bv.y;
        Bs[lcol + 2][lrow] = bv.z; Bs[lcol + 3][lrow] = bv.w;
        __syncthreads();
#pragma unroll
        for (int kk = 0; kk < 16; kk++) {
            float4 a = *(const float4*)&As[kk][ty << 2];
            float4 b = *(const float4*)&Bs[kk][tx << 2];
            acc[0][0] += a.x * b.x; acc[0][1] += a.x * b.y;
            acc[0][2] += a.x * b.z; acc[0][3] += a.x * b.w;
            acc[1][0] += a.y * b.x; acc[1][1] += a.y * b.y;
            acc[1][2] += a.y * b.z; acc[1][3] += a.y * b.w;
            acc[2][0] += a.z * b.x; acc[2][1] += a.z * b.y;
            acc[2][2] += a.z * b.z; acc[2][3] += a.z * b.w;
            acc[3][0] += a.w * b.x; acc[3][1] += a.w * b.y;
            acc[3][2] += a.w * b.z; acc[3][3] += a.w * b.w;
        }
    }
#pragma unroll
    for (int i = 0; i < 4; i++) {
        const int row = m0 + (ty << 2) + i;
        const int col = n0 + (tx << 2);
        float* cp = C + (long)row * N + col;
        atomicAdd(cp + 0, acc[i][0]);
        atomicAdd(cp + 1, acc[i][1]);
        atomicAdd(cp + 2, acc[i][2]);
        atomicAdd(cp + 3, acc[i][3]);
    }
}

// bias init for q / gi / gh before atomic split-K accumulation
__global__ void init_step(const float* __restrict__ ba,
                          const float* __restrict__ b_ih,
                          const float* __restrict__ b_hh)
{
    int idx = blockIdx.x * 256 + threadIdx.x;
    const int nq = BB * HH;
    const int ng = BB * 3 * HH;
    if (idx < nq) {
        g_q[idx] = ba[idx % HH];
    } else if (idx < nq + ng) {
        int i = idx - nq;
        g_gi[i] = b_ih[i % (3 * HH)];
    } else if (idx < nq + 2 * ng) {
        int i = idx - nq - ng;
        g_gh[i] = b_hh[i % (3 * HH)];
    }
}

__global__ void copy_h0(const float* __restrict__ h0)
{
    int i = blockIdx.x * 256 + threadIdx.x;
    float v = h0[i];
    g_h[i] = v;
    g_h16[i] = __float2bfloat16(v);
}

__global__ void write_hidden(float* __restrict__ out_hid)
{
    int i = blockIdx.x * 256 + threadIdx.x;
    out_hid[i] = g_h[i];
}

// ---------------------------------------------------------------------------
// attention scores: grid (64, 4) x 256.  scores[b,s] = Va . tanh(q+keysU) + bv
// ---------------------------------------------------------------------------
__global__ void attn_scores(const float* __restrict__ Va, const float* __restrict__ bv)
{
    __shared__ float qs[HH];
    __shared__ float vs[HH];
    const int b = blockIdx.x;
    const int tid = threadIdx.x;
    for (int i = tid; i < HH; i += 256) { qs[i] = g_q[b * HH + i]; vs[i] = Va[i]; }
    __syncthreads();
    const int warp = tid >> 5, lane = tid & 31;
    const int sbase = blockIdx.y * 16 + warp * 2;
#pragma unroll
    for (int si = 0; si < 2; si++) {
        const int s = sbase + si;
        const float* kp = &g_keysU[((long)(b * SS + s)) * HH];
        float sum = 0.f;
        for (int h = lane; h < HH; h += 32)
            sum += fast_tanh(qs[h] + kp[h]) * vs[h];
#pragma unroll
        for (int o = 16; o; o >>= 1) sum += __shfl_xor_sync(~0u, sum, o);
        if (!lane) g_scores[b * SS + s] = sum + bv[0];
    }
}

// ---------------------------------------------------------------------------
// softmax + context + build x (both halves): grid (64, 4) x 256
// ---------------------------------------------------------------------------
__global__ void attn_ctx(const float* __restrict__ EO, const float* __restrict__ emb,
                         const int* __restrict__ target, float* __restrict__ out_attn,
                         int t)
{
    __shared__ float w[SS];
    const int b = blockIdx.x;
    const int tid = threadIdx.x;
    if (tid < 32) {
        float v0 = g_scores[b * SS + tid], v1 = g_scores[b * SS + tid + 32];
        float mx = fmaxf(v0, v1);
#pragma unroll
        for (int o = 16; o; o >>= 1) mx = fmaxf(mx, __shfl_xor_sync(~0u, mx, o));
        float e0 = expf(v0 - mx), e1 = expf(v1 - mx);
        float sm = e0 + e1;
#pragma unroll
        for (int o = 16; o; o >>= 1) sm += __shfl_xor_sync(~0u, sm, o);
        float inv = 1.f / sm;
        w[tid] = e0 * inv;
        w[tid + 32] = e1 * inv;
        if (blockIdx.y == 0) {
            out_attn[((long)(b * TT + t)) * SS + tid] = e0 * inv;
            out_attn[((long)(b * TT + t)) * SS + tid + 32] = e1 * inv;
        }
    }
    __syncthreads();

    const int h = blockIdx.y * 256 + tid;
    float acc = 0.f;
    const float* ep = &EO[(long)b * SS * HH + h];
#pragma unroll 8
    for (int s = 0; s < SS; s++) acc += w[s] * ep[(long)s * HH];
    g_x[b * 2 * HH + HH + h] = acc;

    const int tok = (t == 0) ? 0 : target[b * TT + t - 1];  // SOS_INDEX = 0
    g_x[b * 2 * HH + h] = emb[(long)tok * HH + h];
}

// GRU pointwise; updates g_h (fp32) and g_h16 (bf16)
__global__ void gru_step()
{
    const int b = blockIdx.x;
    for (int j = threadIdx.x; j < HH; j += 256) {
        const int gbase = b * 3 * HH;
        float ir = g_gi[gbase + j];
        float iz = g_gi[gbase + HH + j];
        float in = g_gi[gbase + 2 * HH + j];
        float hr = g_gh[gbase + j];
        float hz = g_gh[gbase + HH + j];
        float hn = g_gh[gbase + 2 * HH + j];
        float r = 1.f / (1.f + expf(-(ir + hr)));
        float z = 1.f / (1.f + expf(-(iz + hz)));
        float n = tanhf(in + r * hn);
        float ho = g_h[b * HH + j];
        float out = (1.f - z) * n + z * ho;
        g_h[b * HH + j] = out;
        g_h16[b * HH + j] = __float2bfloat16(out);
    }
}

// log_softmax over V per batch row
__global__ void logsoftmax_step(float* __restrict__ out_dec, int t)
{
    __shared__ float red[512];
    const int b = blockIdx.x;
    const int tid = threadIdx.x;
    const float* lg = &g_logits[(long)b * VV];

    float mx = -1e30f;
    for (int v = tid; v < VV; v += 512) mx = fmaxf(mx, lg[v]);
    red[tid] = mx; __syncthreads();
    for (int s = 256; s; s >>= 1) {
        if (tid < s) red[tid] = fmaxf(red[tid], red[tid + s]);
        __syncthreads();
    }
    mx = red[0];
    __syncthreads();

    float sum = 0.f;
    for (int v = tid; v < VV; v += 512) sum += expf(lg[v] - mx);
    red[tid] = sum; __syncthreads();
    for (int s = 256; s; s >>= 1) {
        if (tid < s) red[tid] += red[tid + s];
        __syncthreads();
    }
    const float lse = mx + logf(red[0]);

    float* op = &out_dec[((long)(b * TT + t)) * VV];
    for (int v = tid; v < VV; v += 512) op[v] = lg[v] - lse;
}

// ---------------------------------------------------------------------------
extern "C" void kernel_launch(void* const* d_in, const int* in_sizes, int n_in,
                              void* d_out, int out_size)
{
    const float* EO     = (const float*)d_in[0];   // [B,S,H]
    const float* h0     = (const float*)d_in[1];   // [B,H]
    const int*   target = (const int*)  d_in[2];   // [B,T]
    const float* emb    = (const float*)d_in[3];   // [V,H]
    const float* Wa     = (const float*)d_in[4];   // [H,H]
    const float* ba     = (const float*)d_in[5];
    const float* Ua     = (const float*)d_in[6];   // [H,H]
    const float* bu     = (const float*)d_in[7];
    const float* Va     = (const float*)d_in[8];   // [1,H]
    const float* bvp    = (const float*)d_in[9];
    const float* W_ih   = (const float*)d_in[10];  // [3H,2H]
    const float* W_hh   = (const float*)d_in[11];  // [3H,H]
    const float* b_ih   = (const float*)d_in[12];
    const float* b_hh   = (const float*)d_in[13];
    const float* W_out  = (const float*)d_in[14];  // [V,H]
    const float* b_out  = (const float*)d_in[15];

    float* out      = (float*)d_out;
    float* out_dec  = out;                          // [B,T,V]
    float* out_hid  = out + (long)BB * TT * VV;     // [1,B,H]
    float* out_attn = out_hid + (long)BB * HH;      // [B,T,S]

    float *p_keysU, *p_h, *p_q, *p_x, *p_gi, *p_gh, *p_logits;
    __nv_bfloat16 *p_wout16, *p_eo16, *p_ua16, *p_h16;
    cudaGetSymbolAddress((void**)&p_keysU,  g_keysU);
    cudaGetSymbolAddress((void**)&p_h,      g_h);
    cudaGetSymbolAddress((void**)&p_q,      g_q);
    cudaGetSymbolAddress((void**)&p_x,      g_x);
    cudaGetSymbolAddress((void**)&p_gi,     g_gi);
    cudaGetSymbolAddress((void**)&p_gh,     g_gh);
    cudaGetSymbolAddress((void**)&p_logits, g_logits);
    cudaGetSymbolAddress((void**)&p_wout16, g_wout16);
    cudaGetSymbolAddress((void**)&p_eo16,   g_eo16);
    cudaGetSymbolAddress((void**)&p_ua16,   g_ua16);
    cudaGetSymbolAddress((void**)&p_h16,    g_h16);

    // one-time conversions + keysU on tensor cores
    conv_bf16<<<32000, 256>>>(W_out, p_wout16);
    conv_bf16<<<4096, 256>>>(EO, p_eo16);
    conv_bf16<<<1024, 256>>>(Ua, p_ua16);
    copy_h0<<<BB * HH / 256, 256>>>(h0);

    // keysU[B*S, H] = EO_bf16 @ Ua_bf16^T + bu
    gemm_bf16_mma<<<dim3(HH / 128, BB * SS / 64), 256>>>(p_eo16, p_ua16, bu,
                                                         p_keysU, HH, HH);

    const int initBlocks = (BB * HH + 2 * BB * 3 * HH + 255) / 256;

    for (int t = 0; t < TT; t++) {
        init_step<<<initBlocks, 256>>>(ba, b_ih, b_hh);

        // q = h @ Wa^T (+ba via init), splitK=8
        gemm_tn<<<dim3(HH / 64, 1, 8), 256>>>(p_h, Wa, p_q, HH, HH, HH / 8);

        attn_scores<<<dim3(BB, 4), 256>>>(Va, bvp);
        attn_ctx<<<dim3(BB, 4), 256>>>(EO, emb, target, out_attn, t);

        // gi = x @ W_ih^T, splitK=8 ; gh = h @ W_hh^T, splitK=8
        gemm_tn<<<dim3(3 * HH / 64, 1, 8), 256>>>(p_x, W_ih, p_gi,
                                                  3 * HH, 2 * HH, 2 * HH / 8);
        gemm_tn<<<dim3(3 * HH / 64, 1, 8), 256>>>(p_h, W_hh, p_gh,
                                                  3 * HH, HH, HH / 8);

        gru_step<<<BB, 256>>>();

        // logits = h_bf16 @ W_out_bf16^T + b_out   (tensor cores)
        gemm_bf16_mma<<<dim3(VV / 128, 1), 256>>>(p_h16, p_wout16, b_out,
                                                  p_logits, HH, VV);

        logsoftmax_step<<<BB, 512>>>(out_dec, t);
    }

    write_hidden<<<BB * HH / 256, 256>>>(out_hid);
}